// round 1
// baseline (speedup 1.0000x reference)
#include <cuda_runtime.h>
#include <math.h>

namespace {
constexpr int kB  = 64;
constexpr int kSQ = 1024;
constexpr int kSK = 1024;
constexpr int kD  = 256;
constexpr int kDV = 256;

constexpr int BQ = 64;    // q rows per CTA
constexpr int BK = 64;    // keys per chunk
constexpr int NT = 256;   // threads per CTA

constexpr float kScale   = 0.0625f;
constexpr float kDropP   = 0.1f;
constexpr float kKeepInv = 1.0f / 0.9f;

constexpr int QLD = kD + 4;   // 260, padded to dodge bank conflicts
constexpr int KLD = kD + 4;   // 260
constexpr int VLD = kDV;      // 256
constexpr int SLD = BK + 4;   // 68

struct Smem {
  float Qs[BQ][QLD];   // 66,560 B
  float Ks[BK][KLD];   // 66,560 B
  float Vs[BK][VLD];   // 65,536 B
  float Ss[BQ][SLD];   // 17,408 B  (post-softmax, post-dropout probs)
  float bias[BK];      //     256 B  (additive mask bias)
};
// total: 216,320 B  (< 227 KB sm_103a limit)
}  // namespace

__global__ __launch_bounds__(NT, 1)
void attn_fp32_kernel(const float* __restrict__ q, const float* __restrict__ k,
                      const float* __restrict__ v, const int* __restrict__ mask,
                      const float* __restrict__ du, float* __restrict__ out) {
  extern __shared__ char smem_raw[];
  Smem* sm = reinterpret_cast<Smem*>(smem_raw);

  const int qt  = blockIdx.x;
  const int b   = blockIdx.y;
  const int tid = threadIdx.x;
  const int tx  = tid & 15;   // 0..15
  const int ty  = tid >> 4;   // 0..15
  const int q0  = qt * BQ;

  const int r0  = ty * 4;     // this thread's 4 q-rows
  const int c0  = tx * 4;     // this thread's 4 score cols (S phase)
  const int oc0 = tx * 16;    // this thread's 16 output cols (PV phase)

  // ---- Load Q tile (64 x 256), float4, coalesced ----
  {
    const float4* qg = reinterpret_cast<const float4*>(q + (size_t)(b * kSQ + q0) * kD);
#pragma unroll
    for (int i = tid; i < BQ * kD / 4; i += NT) {
      const int r = i >> 6, c4 = i & 63;
      *reinterpret_cast<float4*>(&sm->Qs[r][c4 * 4]) = qg[i];
    }
  }

  float acc[4][16];
#pragma unroll
  for (int i = 0; i < 4; i++)
#pragma unroll
    for (int j = 0; j < 16; j++) acc[i][j] = 0.f;

  float mrow[4] = {-INFINITY, -INFINITY, -INFINITY, -INFINITY};
  float lrow[4] = {0.f, 0.f, 0.f, 0.f};

  for (int kt = 0; kt < kSK / BK; ++kt) {
    __syncthreads();  // previous PV done reading Ks/Vs/Ss

    // ---- Stage K chunk, V chunk, mask bias ----
    const float4* kg = reinterpret_cast<const float4*>(k + (size_t)(b * kSK + kt * BK) * kD);
    const float4* vg = reinterpret_cast<const float4*>(v + (size_t)(b * kSK + kt * BK) * kDV);
#pragma unroll
    for (int i = tid; i < BK * kD / 4; i += NT) {
      const int r = i >> 6, c4 = i & 63;
      *reinterpret_cast<float4*>(&sm->Ks[r][c4 * 4]) = kg[i];
    }
#pragma unroll
    for (int i = tid; i < BK * kDV / 4; i += NT) {
      const int r = i >> 6, c4 = i & 63;
      *reinterpret_cast<float4*>(&sm->Vs[r][c4 * 4]) = vg[i];
    }
    if (tid < BK) {
      const int mv = mask[b * kSK + kt * BK + tid];
      sm->bias[tid] = -1e9f * (1.0f - (float)mv);
    }
    __syncthreads();

    // ---- S = (Q K^T) for this thread's 4x4 tile ----
    float s[4][4];
#pragma unroll
    for (int i = 0; i < 4; i++)
#pragma unroll
      for (int j = 0; j < 4; j++) s[i][j] = 0.f;

#pragma unroll 2
    for (int d = 0; d < kD; d += 4) {
      float4 qv[4], kv[4];
#pragma unroll
      for (int i = 0; i < 4; i++) qv[i] = *reinterpret_cast<const float4*>(&sm->Qs[r0 + i][d]);
#pragma unroll
      for (int j = 0; j < 4; j++) kv[j] = *reinterpret_cast<const float4*>(&sm->Ks[c0 + j][d]);
#pragma unroll
      for (int i = 0; i < 4; i++) {
#pragma unroll
        for (int j = 0; j < 4; j++) {
          s[i][j] += qv[i].x * kv[j].x;
          s[i][j] += qv[i].y * kv[j].y;
          s[i][j] += qv[i].z * kv[j].z;
          s[i][j] += qv[i].w * kv[j].w;
        }
      }
    }

    // ---- Online softmax update + dropout, per row ----
#pragma unroll
    for (int i = 0; i < 4; i++) {
      float sv[4];
#pragma unroll
      for (int j = 0; j < 4; j++) sv[j] = s[i][j] * kScale + sm->bias[c0 + j];

      float mx = fmaxf(fmaxf(sv[0], sv[1]), fmaxf(sv[2], sv[3]));
#pragma unroll
      for (int off = 8; off >= 1; off >>= 1)
        mx = fmaxf(mx, __shfl_xor_sync(0xffffffffu, mx, off));

      const float mnew = fmaxf(mrow[i], mx);
      const float corr = __expf(mrow[i] - mnew);  // exp(-inf)=0 on first chunk
      mrow[i] = mnew;

      float p[4], rs = 0.f;
#pragma unroll
      for (int j = 0; j < 4; j++) { p[j] = __expf(sv[j] - mnew); rs += p[j]; }
#pragma unroll
      for (int off = 8; off >= 1; off >>= 1)
        rs += __shfl_xor_sync(0xffffffffu, rs, off);

      lrow[i] = lrow[i] * corr + rs;  // normalizer accumulated PRE-dropout (matches ref)

#pragma unroll
      for (int j = 0; j < 16; j++) acc[i][j] *= corr;

      // dropout on the un-normalized numerator
      const float4 u = *reinterpret_cast<const float4*>(
          &du[(size_t)(b * kSQ + q0 + r0 + i) * kSK + kt * BK + c0]);
      p[0] *= (u.x >= kDropP) ? kKeepInv : 0.f;
      p[1] *= (u.y >= kDropP) ? kKeepInv : 0.f;
      p[2] *= (u.z >= kDropP) ? kKeepInv : 0.f;
      p[3] *= (u.w >= kDropP) ? kKeepInv : 0.f;

      *reinterpret_cast<float4*>(&sm->Ss[r0 + i][c0]) = make_float4(p[0], p[1], p[2], p[3]);
    }
    __syncthreads();

    // ---- O += P V for this thread's 4x16 tile ----
#pragma unroll 2
    for (int kk = 0; kk < BK; kk += 4) {
      float4 pr[4];
#pragma unroll
      for (int i = 0; i < 4; i++)
        pr[i] = *reinterpret_cast<const float4*>(&sm->Ss[r0 + i][kk]);
#pragma unroll
      for (int dkk = 0; dkk < 4; dkk++) {
        float4 vv[4];
#pragma unroll
        for (int j = 0; j < 4; j++)
          vv[j] = *reinterpret_cast<const float4*>(&sm->Vs[kk + dkk][oc0 + j * 4]);
#pragma unroll
        for (int i = 0; i < 4; i++) {
          const float ps = (dkk == 0) ? pr[i].x : (dkk == 1) ? pr[i].y
                          : (dkk == 2) ? pr[i].z : pr[i].w;
#pragma unroll
          for (int j = 0; j < 4; j++) {
            acc[i][j * 4 + 0] += ps * vv[j].x;
            acc[i][j * 4 + 1] += ps * vv[j].y;
            acc[i][j * 4 + 2] += ps * vv[j].z;
            acc[i][j * 4 + 3] += ps * vv[j].w;
          }
        }
      }
    }
  }

  // ---- Epilogue: normalize by l and store ----
  float* ob = out + (size_t)(b * kSQ + q0) * kDV;
#pragma unroll
  for (int i = 0; i < 4; i++) {
    const float invl = 1.0f / lrow[i];
    float4* orow = reinterpret_cast<float4*>(ob + (size_t)(r0 + i) * kDV + oc0);
#pragma unroll
    for (int j = 0; j < 4; j++) {
      orow[j] = make_float4(acc[i][j * 4 + 0] * invl, acc[i][j * 4 + 1] * invl,
                            acc[i][j * 4 + 2] * invl, acc[i][j * 4 + 3] * invl);
    }
  }
}

extern "C" void kernel_launch(void* const* d_in, const int* in_sizes, int n_in,
                              void* d_out, int out_size) {
  const float* q    = (const float*)d_in[0];
  const float* k    = (const float*)d_in[1];
  const float* v    = (const float*)d_in[2];
  const int*   mask = (const int*)d_in[3];
  const float* du   = (const float*)d_in[4];
  float* out = (float*)d_out;

  cudaFuncSetAttribute(attn_fp32_kernel,
                       cudaFuncAttributeMaxDynamicSharedMemorySize,
                       (int)sizeof(Smem));

  dim3 grid(kSQ / BQ, kB);  // 16 q-tiles x 64 batches = 1024 CTAs
  attn_fp32_kernel<<<grid, NT, sizeof(Smem)>>>(q, k, v, mask, du, out);
}

// round 2
// speedup vs baseline: 1.8209x; 1.8209x over previous
#include <cuda_runtime.h>
#include <math.h>

namespace {
constexpr int kB  = 64;
constexpr int kSQ = 1024;
constexpr int kSK = 1024;
constexpr int kD  = 256;
constexpr int kDV = 256;

constexpr int BQ = 64;    // q rows per CTA
constexpr int BK = 64;    // keys per chunk
constexpr int NT = 256;   // threads per CTA

constexpr float kScale   = 0.0625f;
constexpr float kDropP   = 0.1f;
constexpr float kKeepInv = 1.0f / 0.9f;

constexpr int SLD = BK + 4;   // 68, Ss row stride

// Qt/Kt: d-major, 64 floats per d-row, XOR-swizzled at float4 granularity.
// float index for element (d, r):
//   d*64 + (((r>>2) ^ ((d>>2)&15)) << 2) + (r&3)
__device__ __forceinline__ int qk_off(int d, int r) {
  return d * 64 + ((((r >> 2) ^ ((d >> 2) & 15)) << 2) | (r & 3));
}

struct Smem {
  float Qt[kD * BQ];    // 65,536 B  (Q^T, swizzled)
  float Kt[kD * BK];    // 65,536 B  (K^T, swizzled)
  float Vs[BK][kDV];    // 65,536 B  (row-major)
  float Ss[BQ][SLD];    // 17,408 B  (post-softmax, post-dropout probs)
  float bias[BK];       //    256 B
};
// total: 214,272 B (< 227 KB limit)
}  // namespace

__global__ __launch_bounds__(NT, 1)
void attn_fp32_kernel(const float* __restrict__ q, const float* __restrict__ k,
                      const float* __restrict__ v, const int* __restrict__ mask,
                      const float* __restrict__ du, float* __restrict__ out) {
  extern __shared__ char smem_raw[];
  Smem* sm = reinterpret_cast<Smem*>(smem_raw);

  const int qt  = blockIdx.x;
  const int b   = blockIdx.y;
  const int tid = threadIdx.x;
  const int tx  = tid & 15;   // 0..15: score-col group / output-col group
  const int ty  = tid >> 4;   // 0..15: row group
  const int q0  = qt * BQ;

  const int r0 = ty * 4;      // this thread's 4 q-rows
  const int c0 = tx * 4;      // this thread's 4 score cols

  // ---- Stage Q transposed+swizzled (coalesced global reads) ----
  {
    const float4* qg = reinterpret_cast<const float4*>(q + (size_t)(b * kSQ + q0) * kD);
    for (int i = tid; i < BQ * kD / 4; i += NT) {
      const int r = i >> 6, c4 = i & 63;
      const float4 x = qg[i];
      const int d = 4 * c4;
      sm->Qt[qk_off(d + 0, r)] = x.x;
      sm->Qt[qk_off(d + 1, r)] = x.y;
      sm->Qt[qk_off(d + 2, r)] = x.z;
      sm->Qt[qk_off(d + 3, r)] = x.w;
    }
  }

  float acc[4][16];   // acc[i][jj*4+e]: out col = 4*tx + 64*jj + e
#pragma unroll
  for (int i = 0; i < 4; i++)
#pragma unroll
    for (int j = 0; j < 16; j++) acc[i][j] = 0.f;

  float mrow[4] = {-INFINITY, -INFINITY, -INFINITY, -INFINITY};
  float lrow[4] = {0.f, 0.f, 0.f, 0.f};

  for (int kt = 0; kt < kSK / BK; ++kt) {
    __syncthreads();  // previous PV done reading Kt/Vs/Ss

    // ---- Stage K chunk (transposed+swizzled), V chunk (row-major), bias ----
    const float4* kg = reinterpret_cast<const float4*>(k + (size_t)(b * kSK + kt * BK) * kD);
    const float4* vg = reinterpret_cast<const float4*>(v + (size_t)(b * kSK + kt * BK) * kDV);
    for (int i = tid; i < BK * kD / 4; i += NT) {
      const int r = i >> 6, c4 = i & 63;
      const float4 x = kg[i];
      const int d = 4 * c4;
      sm->Kt[qk_off(d + 0, r)] = x.x;
      sm->Kt[qk_off(d + 1, r)] = x.y;
      sm->Kt[qk_off(d + 2, r)] = x.z;
      sm->Kt[qk_off(d + 3, r)] = x.w;
    }
    for (int i = tid; i < BK * kDV / 4; i += NT) {
      const int r = i >> 6, c4 = i & 63;
      *reinterpret_cast<float4*>(&sm->Vs[r][c4 * 4]) = vg[i];
    }
    if (tid < BK) {
      const int mv = mask[b * kSK + kt * BK + tid];
      sm->bias[tid] = -1e9f * (1.0f - (float)mv);
    }
    __syncthreads();

    // ---- S = Q K^T : per-thread 4x4 tile, conflict-free fragment loads ----
    float s[4][4];
#pragma unroll
    for (int i = 0; i < 4; i++)
#pragma unroll
      for (int j = 0; j < 4; j++) s[i][j] = 0.f;

#pragma unroll 4
    for (int d = 0; d < kD; ++d) {
      const int sw = (d >> 2) & 15;
      const float4 qv = *reinterpret_cast<const float4*>(&sm->Qt[d * 64 + ((ty ^ sw) << 2)]);
      const float4 kv = *reinterpret_cast<const float4*>(&sm->Kt[d * 64 + ((tx ^ sw) << 2)]);
      const float qa[4] = {qv.x, qv.y, qv.z, qv.w};
      const float ka[4] = {kv.x, kv.y, kv.z, kv.w};
#pragma unroll
      for (int i = 0; i < 4; i++)
#pragma unroll
        for (int j = 0; j < 4; j++) s[i][j] += qa[i] * ka[j];
    }

    // ---- Online softmax update + dropout, per row ----
#pragma unroll
    for (int i = 0; i < 4; i++) {
      float sv[4];
#pragma unroll
      for (int j = 0; j < 4; j++) sv[j] = s[i][j] * kScale + sm->bias[c0 + j];

      float mx = fmaxf(fmaxf(sv[0], sv[1]), fmaxf(sv[2], sv[3]));
#pragma unroll
      for (int off = 8; off >= 1; off >>= 1)
        mx = fmaxf(mx, __shfl_xor_sync(0xffffffffu, mx, off));

      const float mnew = fmaxf(mrow[i], mx);
      const float corr = __expf(mrow[i] - mnew);  // exp(-inf)=0 on first chunk
      mrow[i] = mnew;

      float p[4], rs = 0.f;
#pragma unroll
      for (int j = 0; j < 4; j++) { p[j] = __expf(sv[j] - mnew); rs += p[j]; }
#pragma unroll
      for (int off = 8; off >= 1; off >>= 1)
        rs += __shfl_xor_sync(0xffffffffu, rs, off);

      lrow[i] = lrow[i] * corr + rs;  // normalizer accumulated PRE-dropout (matches ref)

#pragma unroll
      for (int j = 0; j < 16; j++) acc[i][j] *= corr;

      // dropout on the un-normalized numerator
      const float4 u = *reinterpret_cast<const float4*>(
          &du[(size_t)(b * kSQ + q0 + r0 + i) * kSK + kt * BK + c0]);
      p[0] *= (u.x >= kDropP) ? kKeepInv : 0.f;
      p[1] *= (u.y >= kDropP) ? kKeepInv : 0.f;
      p[2] *= (u.z >= kDropP) ? kKeepInv : 0.f;
      p[3] *= (u.w >= kDropP) ? kKeepInv : 0.f;

      *reinterpret_cast<float4*>(&sm->Ss[r0 + i][c0]) = make_float4(p[0], p[1], p[2], p[3]);
    }
    __syncthreads();

    // ---- O += P V : out cols strided (4*tx + 64*jj) => conflict-free V reads ----
#pragma unroll 2
    for (int kk = 0; kk < BK; kk += 4) {
      float4 pr[4];
#pragma unroll
      for (int i = 0; i < 4; i++)
        pr[i] = *reinterpret_cast<const float4*>(&sm->Ss[r0 + i][kk]);
#pragma unroll
      for (int dkk = 0; dkk < 4; dkk++) {
        float4 vv[4];
#pragma unroll
        for (int jj = 0; jj < 4; jj++)
          vv[jj] = *reinterpret_cast<const float4*>(&sm->Vs[kk + dkk][4 * tx + 64 * jj]);
#pragma unroll
        for (int i = 0; i < 4; i++) {
          const float ps = (dkk == 0) ? pr[i].x : (dkk == 1) ? pr[i].y
                          : (dkk == 2) ? pr[i].z : pr[i].w;
#pragma unroll
          for (int jj = 0; jj < 4; jj++) {
            acc[i][jj * 4 + 0] += ps * vv[jj].x;
            acc[i][jj * 4 + 1] += ps * vv[jj].y;
            acc[i][jj * 4 + 2] += ps * vv[jj].z;
            acc[i][jj * 4 + 3] += ps * vv[jj].w;
          }
        }
      }
    }
  }

  // ---- Epilogue: normalize by l and store (coalesced 16B per lane) ----
  float* ob = out + (size_t)(b * kSQ + q0) * kDV;
#pragma unroll
  for (int i = 0; i < 4; i++) {
    const float invl = 1.0f / lrow[i];
#pragma unroll
    for (int jj = 0; jj < 4; jj++) {
      float4 o;
      o.x = acc[i][jj * 4 + 0] * invl;
      o.y = acc[i][jj * 4 + 1] * invl;
      o.z = acc[i][jj * 4 + 2] * invl;
      o.w = acc[i][jj * 4 + 3] * invl;
      *reinterpret_cast<float4*>(ob + (size_t)(r0 + i) * kDV + 4 * tx + 64 * jj) = o;
    }
  }
}

extern "C" void kernel_launch(void* const* d_in, const int* in_sizes, int n_in,
                              void* d_out, int out_size) {
  const float* q    = (const float*)d_in[0];
  const float* k    = (const float*)d_in[1];
  const float* v    = (const float*)d_in[2];
  const int*   mask = (const int*)d_in[3];
  const float* du   = (const float*)d_in[4];
  float* out = (float*)d_out;

  cudaFuncSetAttribute(attn_fp32_kernel,
                       cudaFuncAttributeMaxDynamicSharedMemorySize,
                       (int)sizeof(Smem));

  dim3 grid(kSQ / BQ, kB);  // 16 q-tiles x 64 batches = 1024 CTAs
  attn_fp32_kernel<<<grid, NT, sizeof(Smem)>>>(q, k, v, mask, du, out);
}